// round 8
// baseline (speedup 1.0000x reference)
#include <cuda_runtime.h>

// Problem constants (fixed by the reference)
#define BB   4
#define CC   32
#define HH   64
#define WW   64
#define KK   64
#define HWV  (HH*WW)      // 4096
#define BCV  (BB*CC)      // 128
#define CAP  1024         // max support pixels per RF (analysis: <= ~930)
#define MAXJ 68           // max padded RFs per pixel (<= KK+3 pad)

// ---------------- static device scratch (no allocation allowed) -------------
__device__ int g_cnt[KK];        // support size per k
__device__ int g_pk [KK*CAP];    // per-k list, packed {rf20bits | pixel12}
__device__ int g_pxc[HWV];       // per-pixel active-k count
__device__ int g_invp[HWV];      // pixel -> sorted position
__device__ int g_spix[HWV];      // sorted position -> pixel
__device__ int g_scnt[HWV];      // padded count at sorted position
__device__ int g_pxt[MAXJ*HWV];  // per-pixel lists (j-major, SORTED pos), {rf25|k7}

__device__ __forceinline__ float ex2_fast(float y) {
    float r;
    asm("ex2.approx.f32 %0, %1;" : "=f"(r) : "f"(y));
    return r;
}

// ---------------- P1: per-k lists (blocks 0..63) + per-pixel counts (64..67) -
__global__ __launch_bounds__(1024) void prep1(const float* __restrict__ rfs) {
    const int tid = threadIdx.x;
    const float LOG2E = 1.4426950408889634f;

    if (blockIdx.x < 64) {
        const int k    = blockIdx.x;
        const int lane = tid & 31;
        const int wid  = tid >> 5;
        __shared__ int wtot[32];
        __shared__ int woff[32];

        const float4 r = ((const float4*)(rfs + k*HWV))[tid];
        const int f0 = (r.x != 0.0f), f1 = (r.y != 0.0f), f2 = (r.z != 0.0f), f3 = (r.w != 0.0f);
        const int cnt = f0 + f1 + f2 + f3;

        int s = cnt;
        #pragma unroll
        for (int o = 1; o < 32; o <<= 1) {
            int t = __shfl_up_sync(0xffffffffu, s, o);
            if (lane >= o) s += t;
        }
        const int excl = s - cnt;
        if (lane == 31) wtot[wid] = s;
        __syncthreads();
        if (wid == 0) {
            int v = wtot[lane], ss = v;
            #pragma unroll
            for (int o = 1; o < 32; o <<= 1) {
                int t = __shfl_up_sync(0xffffffffu, ss, o);
                if (lane >= o) ss += t;
            }
            woff[lane] = ss - v;
            if (lane == 31) g_cnt[k] = (ss < CAP) ? ss : CAP;
        }
        __syncthreads();

        int base = woff[wid] + excl;
        const int p0 = tid * 4;
        int* __restrict__ dst = g_pk + k*CAP;
        #define PACK_A(val, pix) (((__float_as_int((val)*LOG2E) + 0x800) & 0xFFFFF000) | (pix))
        if (f0 && base < CAP) { dst[base] = PACK_A(r.x, p0);     base++; }
        if (f1 && base < CAP) { dst[base] = PACK_A(r.y, p0 + 1); base++; }
        if (f2 && base < CAP) { dst[base] = PACK_A(r.z, p0 + 2); base++; }
        if (f3 && base < CAP) { dst[base] = PACK_A(r.w, p0 + 3); base++; }
        #undef PACK_A
    } else {
        // per-pixel RF counts, dense: 4 blocks x 1024 threads = 4096 pixels
        const int p = (blockIdx.x - 64) * 1024 + tid;
        int c = 0;
        #pragma unroll 8
        for (int k = 0; k < KK; k++) c += (rfs[k*HWV + p] != 0.0f);
        g_pxc[p] = c;
    }
}

// ---------------- P2: counting sort of pixels by RF count -------------------
// Placement within a bucket uses smem atomic cursors: the resulting
// permutation may vary, but every pixel's h value is computed privately in
// fixed j-order and stored at hs[pixel] -> output is bit-identical.
__global__ __launch_bounds__(1024) void sortk() {
    __shared__ int hist[KK + 1];
    __shared__ int offs[KK + 1];
    const int tid = threadIdx.x;
    if (tid <= KK) hist[tid] = 0;
    __syncthreads();
    int c[4];
    #pragma unroll
    for (int q = 0; q < 4; q++) {
        c[q] = g_pxc[tid + q*1024];
        atomicAdd(&hist[c[q]], 1);
    }
    __syncthreads();
    if (tid == 0) {
        int run = 0;
        for (int i = 0; i <= KK; i++) { offs[i] = run; run += hist[i]; }
    }
    __syncthreads();
    #pragma unroll
    for (int q = 0; q < 4; q++) {
        const int p   = tid + q*1024;
        const int pos = atomicAdd(&offs[c[q]], 1);
        g_invp[p]    = pos;
        g_spix[pos]  = p;
    }
}

// ---------------- P3: transposed per-pixel lists at sorted positions --------
// Pad to a multiple of 4 with null entries {rf=+0, k=64}: ex2(0)*inv[64] = 0.
__global__ __launch_bounds__(1024) void prep2(const float* __restrict__ rfs) {
    const int p   = blockIdx.x * 1024 + threadIdx.x;
    const int pos = g_invp[p];
    const float LOG2E = 1.4426950408889634f;
    int c = 0;
    #pragma unroll 8
    for (int k = 0; k < KK; k++) {
        const float v = rfs[k*HWV + p];
        if (v != 0.0f) {
            // rf*log2e rounded to keep 7 low bits for k (k in 0..63, 64 = pad)
            const int bits = ((__float_as_int(v * LOG2E) + 0x40) & 0xFFFFFF80) | k;
            g_pxt[c*HWV + pos] = bits;
            c++;
        }
    }
    const int cp = (c + 3) & ~3;
    for (int j = c; j < cp; j++) g_pxt[j*HWV + pos] = 64;  // null entry
    g_scnt[pos] = cp;
}

// ---------------- MAIN: one block per bc, two passes, ONE barrier -----------
// exp(v - m)/(exp(-m) + sum exp(v - m)) == exp(v)/(1 + sum exp(v)).
// Pass A: warp w reduces denominators of k = 2w, 2w+1 (pure shfl).
// Pass B: thread owns 4 SORTED positions (count-uniform within each warp),
//         branch-free chunk-of-4 inner loop, register accumulation, no scatter.
__global__ __launch_bounds__(1024) void rf_main(const float* __restrict__ u,
                                                float* __restrict__ out) {
    __shared__ float us[HWV];        // 16 KB input tile
    __shared__ float hs[HWV];        // 16 KB h exchange for pooling
    __shared__ float inv_s[128];     // [64..127] = 0 for pad entries

    const int bc   = blockIdx.x;
    const int tid  = threadIdx.x;
    const int lane = tid & 31;
    const int wid  = tid >> 5;

    ((float4*)us)[tid] = ((const float4*)(u + bc*HWV))[tid];
    if (tid >= 64 && tid < 128) inv_s[tid] = 0.0f;
    __syncthreads();

    // ---- pass A: denominators, warp-per-k ----
    #pragma unroll
    for (int i = 0; i < 2; i++) {
        const int k = wid*2 + i;
        const int n = g_cnt[k];
        const int* __restrict__ pr = g_pk + k*CAP;

        float sum = 0.0f;
        #pragma unroll 4
        for (int j = lane; j < n; j += 32) {
            const int bits = pr[j];                       // coalesced LDG.32
            sum += ex2_fast(us[bits & 0xFFF] * __int_as_float(bits & 0xFFFFF000));
        }
        #pragma unroll
        for (int o = 16; o > 0; o >>= 1) sum += __shfl_down_sync(0xffffffffu, sum, o);
        if (lane == 0) inv_s[k] = 1.0f / (1.0f + sum);
    }
    __syncthreads();                                      // the only barrier

    // ---- pass B: per-pixel numerators at sorted positions ----
    #pragma unroll
    for (int q = 0; q < 4; q++) {
        const int pos = tid + q*1024;
        const int n   = g_scnt[pos];                      // multiple of 4
        const int pix = g_spix[pos];
        const float uu = us[pix];
        float acc = 0.0f;
        for (int j = 0; j < n; j += 4) {
            const int* __restrict__ pb = g_pxt + j*HWV + pos;
            const int b0 = pb[0];                         // 4 independent,
            const int b1 = pb[HWV];                       // coalesced LDGs
            const int b2 = pb[2*HWV];
            const int b3 = pb[3*HWV];
            acc += ex2_fast(uu * __int_as_float(b0 & 0xFFFFFF80)) * inv_s[b0 & 127];
            acc += ex2_fast(uu * __int_as_float(b1 & 0xFFFFFF80)) * inv_s[b1 & 127];
            acc += ex2_fast(uu * __int_as_float(b2 & 0xFFFFFF80)) * inv_s[b2 & 127];
            acc += ex2_fast(uu * __int_as_float(b3 & 0xFFFFFF80)) * inv_s[b3 & 127];
        }
        hs[pix] = acc;
    }
    __syncthreads();

    // ---- 2x2 max pool: one output per thread ----
    const int oh = tid >> 5;
    const int ow = tid & 31;
    float best = 0.0f;                   // h >= 0 always (matches reference)
    #pragma unroll
    for (int dy = 0; dy < 2; dy++) {
        #pragma unroll
        for (int dx = 0; dx < 2; dx++)
            best = fmaxf(best, hs[(2*oh + dy)*WW + 2*ow + dx]);
    }
    out[bc*1024 + tid] = best;
}

// ---------------- launch -----------------------------------------------------
extern "C" void kernel_launch(void* const* d_in, const int* in_sizes, int n_in,
                              void* d_out, int out_size) {
    const float* u   = (const float*)d_in[0];   // (4,32,64,64)
    const float* rfs = (const float*)d_in[1];   // (64,64,64)
    float* out = (float*)d_out;                 // (4,32,32,32)

    prep1  <<<68,  1024>>>(rfs);
    sortk  <<<1,   1024>>>();
    prep2  <<<4,   1024>>>(rfs);
    rf_main<<<BCV, 1024>>>(u, out);
}

// round 9
// speedup vs baseline: 1.6088x; 1.6088x over previous
#include <cuda_runtime.h>

// Problem constants (fixed by the reference)
#define BB   4
#define CC   32
#define HH   64
#define WW   64
#define KK   64
#define HWV  (HH*WW)      // 4096
#define BCV  (BB*CC)      // 128
#define CAP  1024         // max support pixels per RF (analysis: <= ~930)
#define MAXC 16           // max chunks of 4 per pixel (<= ceil(64/4))

// ---------------- static device scratch (no allocation allowed) -------------
__device__ int   g_cnt [KK];          // PADDED (x4) support size per k
__device__ float g_base[KK];          // 1.0f - (#pad entries) per k
__device__ int   g_pk  [KK*CAP];      // per-k list, packed {rf20 | pixel12}
__device__ int   g_pxc [HWV];         // per-pixel CHUNK count (padded/4)
__device__ int   g_pxt [MAXC*HWV*4];  // per-pixel lists, chunk-major int4,
                                      // packed {rf25 | k7}; k=64 -> null

__device__ __forceinline__ float ex2_fast(float y) {
    float r;
    asm("ex2.approx.f32 %0, %1;" : "=f"(r) : "f"(y));
    return r;
}

// ---------------- PREP (single kernel, 80 blocks) ---------------------------
// blocks 0..63 : per-k compact support list (raster order, padded to x4)
// blocks 64..79: per-pixel transposed lists, 256 pixels/block, k ascending
// All orders fixed -> deterministic.
__global__ __launch_bounds__(1024) void prep(const float* __restrict__ rfs) {
    const int tid = threadIdx.x;
    const float LOG2E = 1.4426950408889634f;

    __shared__ int wtot[32];
    __shared__ int woff[32];
    __shared__ int qc[4][256];

    if (blockIdx.x < 64) {
        const int k    = blockIdx.x;
        const int lane = tid & 31;
        const int wid  = tid >> 5;

        const float4 r = ((const float4*)(rfs + k*HWV))[tid];
        const int f0 = (r.x != 0.0f), f1 = (r.y != 0.0f), f2 = (r.z != 0.0f), f3 = (r.w != 0.0f);
        const int cnt = f0 + f1 + f2 + f3;

        int s = cnt;
        #pragma unroll
        for (int o = 1; o < 32; o <<= 1) {
            int t = __shfl_up_sync(0xffffffffu, s, o);
            if (lane >= o) s += t;
        }
        const int excl = s - cnt;
        if (lane == 31) wtot[wid] = s;
        __syncthreads();
        if (wid == 0) {
            int v = wtot[lane], ss = v;
            #pragma unroll
            for (int o = 1; o < 32; o <<= 1) {
                int t = __shfl_up_sync(0xffffffffu, ss, o);
                if (lane >= o) ss += t;
            }
            woff[lane] = ss - v;
            if (lane == 31) {
                const int n  = (ss < CAP) ? ss : CAP;
                const int n4 = (n + 3) & ~3;
                g_cnt[k]  = n4;
                g_base[k] = 1.0f - (float)(n4 - n);
                // pad entries: {rf=+0, pixel=0} -> contributes exp(0)=1,
                // exactly cancelled by g_base. Disjoint from real writes.
                for (int j = n; j < n4; j++) g_pk[k*CAP + j] = 0;
            }
        }
        __syncthreads();

        int base = woff[wid] + excl;
        const int p0 = tid * 4;
        int* __restrict__ dst = g_pk + k*CAP;
        #define PACK_A(val, pix) (((__float_as_int((val)*LOG2E) + 0x800) & 0xFFFFF000) | (pix))
        if (f0 && base < CAP) { dst[base] = PACK_A(r.x, p0);     base++; }
        if (f1 && base < CAP) { dst[base] = PACK_A(r.y, p0 + 1); base++; }
        if (f2 && base < CAP) { dst[base] = PACK_A(r.z, p0 + 2); base++; }
        if (f3 && base < CAP) { dst[base] = PACK_A(r.w, p0 + 3); base++; }
        #undef PACK_A
    } else {
        // 1024 threads = 256 pixels x 4 k-quarters (16 k each).
        const int q  = tid >> 8;
        const int pl = tid & 255;
        const int p  = (blockIdx.x - 64) * 256 + pl;

        // hold this thread's 16 rf values in registers (statically indexed)
        float rv[16];
        int c = 0;
        #pragma unroll
        for (int i = 0; i < 16; i++) {
            rv[i] = rfs[(q*16 + i)*HWV + p];
            c += (rv[i] != 0.0f);
        }
        qc[q][pl] = c;
        __syncthreads();

        int off = 0;
        #pragma unroll
        for (int qq = 0; qq < 4; qq++) if (qq < q) off += qc[qq][pl];

        #pragma unroll
        for (int i = 0; i < 16; i++) {
            if (rv[i] != 0.0f) {
                const int k    = q*16 + i;
                const int bits = ((__float_as_int(rv[i] * LOG2E) + 0x40) & 0xFFFFFF80) | k;
                g_pxt[((off >> 2)*HWV + p)*4 + (off & 3)] = bits;
                off++;
            }
        }
        if (q == 3) {                       // off == grand total here
            int tot = off;
            while (tot & 3) {               // pad to x4 with null (k=64)
                g_pxt[((tot >> 2)*HWV + p)*4 + (tot & 3)] = 64;
                tot++;
            }
            g_pxc[p] = tot >> 2;            // chunk count
        }
    }
}

// ---------------- MAIN: one block per bc, two passes, ONE barrier -----------
// exp(v - m)/(exp(-m) + sum exp(v - m)) == exp(v)/(1 + sum exp(v)).
// Pass A: warp w reduces denominators of k = 2w, 2w+1 (pure shfl, guard-free
//         thanks to padding + g_base correction).
// Pass B: thread owns 4 consecutive-pixel positions; chunk-major int4 lists
//         give one coalesced LDG.128 per chunk, 4 independent per iteration.
__global__ __launch_bounds__(1024) void rf_main(const float* __restrict__ u,
                                                float* __restrict__ out) {
    __shared__ float us[HWV];        // 16 KB input tile
    __shared__ float hs[HWV];        // 16 KB h exchange for pooling
    __shared__ float inv_s[128];     // [64..127] = 0 for null entries

    const int bc   = blockIdx.x;
    const int tid  = threadIdx.x;
    const int lane = tid & 31;
    const int wid  = tid >> 5;

    ((float4*)us)[tid] = ((const float4*)(u + bc*HWV))[tid];
    if (tid >= 64 && tid < 128) inv_s[tid] = 0.0f;
    __syncthreads();

    // ---- pass A: denominators, warp-per-k ----
    #pragma unroll
    for (int i = 0; i < 2; i++) {
        const int k  = wid*2 + i;
        const int n4 = g_cnt[k];
        const int* __restrict__ pr = g_pk + k*CAP;

        float sum = 0.0f;
        #pragma unroll 4
        for (int j = lane; j < n4; j += 32) {
            const int bits = pr[j];                       // coalesced LDG.32
            sum += ex2_fast(us[bits & 0xFFF] * __int_as_float(bits & 0xFFFFF000));
        }
        #pragma unroll
        for (int o = 16; o > 0; o >>= 1) sum += __shfl_down_sync(0xffffffffu, sum, o);
        if (lane == 0) inv_s[k] = 1.0f / (g_base[k] + sum);
    }
    __syncthreads();                                      // the only barrier

    // ---- pass B: per-pixel numerators, 4 interleaved pixels, int4 chunks ---
    float uu[4], acc[4];
    int   nc[4];
    #pragma unroll
    for (int q = 0; q < 4; q++) {
        const int p = tid + q*1024;
        nc[q]  = g_pxc[p];
        uu[q]  = us[p];
        acc[q] = 0.0f;
    }
    const int cmax = max(max(nc[0], nc[1]), max(nc[2], nc[3]));
    const int4* __restrict__ PT = (const int4*)g_pxt;

    for (int c = 0; c < cmax; c++) {
        #pragma unroll
        for (int q = 0; q < 4; q++) {
            if (c < nc[q]) {
                const int4 b = PT[c*HWV + tid + q*1024];  // LDG.128 coalesced
                acc[q] += ex2_fast(uu[q] * __int_as_float(b.x & 0xFFFFFF80)) * inv_s[b.x & 127];
                acc[q] += ex2_fast(uu[q] * __int_as_float(b.y & 0xFFFFFF80)) * inv_s[b.y & 127];
                acc[q] += ex2_fast(uu[q] * __int_as_float(b.z & 0xFFFFFF80)) * inv_s[b.z & 127];
                acc[q] += ex2_fast(uu[q] * __int_as_float(b.w & 0xFFFFFF80)) * inv_s[b.w & 127];
            }
        }
    }

    #pragma unroll
    for (int q = 0; q < 4; q++) hs[tid + q*1024] = acc[q];
    __syncthreads();

    // ---- 2x2 max pool: one output per thread ----
    const int oh = tid >> 5;
    const int ow = tid & 31;
    float best = 0.0f;                   // h >= 0 always (matches reference)
    #pragma unroll
    for (int dy = 0; dy < 2; dy++) {
        #pragma unroll
        for (int dx = 0; dx < 2; dx++)
            best = fmaxf(best, hs[(2*oh + dy)*WW + 2*ow + dx]);
    }
    out[bc*1024 + tid] = best;
}

// ---------------- launch -----------------------------------------------------
extern "C" void kernel_launch(void* const* d_in, const int* in_sizes, int n_in,
                              void* d_out, int out_size) {
    const float* u   = (const float*)d_in[0];   // (4,32,64,64)
    const float* rfs = (const float*)d_in[1];   // (64,64,64)
    float* out = (float*)d_out;                 // (4,32,32,32)

    prep   <<<80,  1024>>>(rfs);
    rf_main<<<BCV, 1024>>>(u, out);
}